// round 14
// baseline (speedup 1.0000x reference)
#include <cuda_runtime.h>

// MBTR + analytic divergence, GB300 (sm_103a). Round 11 = R8 +
//   float4 epilogue: 192 threads each own one fixed float4 (4 cells, 2 atoms)
//   across all 16 (e1,e2) slots; acc loaded once, 16 STG.128 instead of
//   48 STG.32 + per-cell address math. BAND 5.0.
//
// Block = (b, g-chunk of 32, atom-sixth of 8). Warp = one atom, lane = one g.
// Band skip: pair irrelevant unless gfs in [gg_lo-5, gg_hi+5] sigma.
// Warp-uniform predicate -> 48-bit mask via 2 ballots, iterate set bits.
// mbtr via coalesced global atomicAdd into pre-zeroed region (zero kernel).

#define NB   32
#define NA   48
#define NE   4
#define NG   128
#define ATH  8                  // atoms per block
#define GC   32                 // grid points per block
#define NTHR (ATH * GC)         // 256
#define NTHIRD (NA / ATH)       // 6
#define NGCH   (NG / GC)        // 4
#define NBLK (NB * NGCH * NTHIRD)   // 768
#define MBTR_SZ (NB * NE * NE * NG) // 65536
#define ROWQ (ATH * 3)          // 24 floats per (slot,g) row owned by block
#define ACCPAD (ROWQ + 1)       // 25
#define NF4  (GC * ROWQ / 4)    // 192 float4 per slot per block

static __device__ __forceinline__ float ex2f(float x) {
    float y;
    asm("ex2.approx.ftz.f32 %0, %1;" : "=f"(y) : "f"(x));
    return y;
}

__global__ void zero_mbtr(float4* __restrict__ out) {
    out[blockIdx.x * 1024 + threadIdx.x] = make_float4(0.f, 0.f, 0.f, 0.f);
}

__global__ void __launch_bounds__(NTHR, 4)
mbtr_kernel(const float* __restrict__ r,
            const int*   __restrict__ z,
            const float* __restrict__ grid,
            float*       __restrict__ out)
{
    const int bid    = blockIdx.x;
    const int third  = bid % NTHIRD;
    const int tmp    = bid / NTHIRD;
    const int gchunk = tmp % NGCH;
    const int b      = tmp / NGCH;

    const int t    = threadIdx.x;
    const int al   = t >> 5;            // warp id = local atom
    const int lane = t & 31;
    const int a    = third * ATH + al;  // global atom
    const int g    = gchunk * GC + lane;

    __shared__ float4 tabA[NA][ATH];    // {gfs, wf*C, gsq, -ux}
    __shared__ float2 tabB[NA][ATH];    // {-uy, -uz}
    __shared__ float  gfsT[ATH][NA];    // gfs, lane-major readable
    __shared__ float  acc[NE][GC][ACCPAD];
    __shared__ float4 rs[NA];
    __shared__ int    zs[NA], S[NA], segs[NE + 1];

    const float INV_SIGMA = 20.0f;
    const float CM        = -0.72134752044448170f;   // -0.5 * log2(e)
    const float BAND      = 5.0f;                    // sigma units

    if (t < NA) {
        zs[t] = z[t];
        const float* rp = r + (b * NA + t) * 3;
        rs[t] = make_float4(rp[0], rp[1], rp[2], 0.f);
    }
    __syncthreads();

    if (t == 0) {
        int cnt[NE] = {0, 0, 0, 0};
        for (int j = 0; j < NA; j++) cnt[zs[j]]++;
        int off = 0, pos[NE];
        segs[0] = 0;
        #pragma unroll
        for (int e = 0; e < NE; e++) { pos[e] = off; off += cnt[e]; segs[e + 1] = off; }
        for (int j = 0; j < NA; j++) S[pos[zs[j]]++] = j;
    }
    __syncthreads();

    // Pair table: 48 partners x 8 local atoms = 384 entries over 256 threads.
    {
        const float gdx = grid[1] - grid[0];
        const float C   = gdx * 0.3989422804014327f * INV_SIGMA;
        for (int f = t; f < NA * ATH; f += NTHR) {
            const int jp  = f >> 3;
            const int al2 = f & (ATH - 1);
            const int a2  = third * ATH + al2;
            const int p   = S[jp];
            if (p == a2) {
                tabA[jp][al2] = make_float4(0.f, 0.f, 0.f, 0.f);
                tabB[jp][al2] = make_float2(0.f, 0.f);
                gfsT[al2][jp] = 0.f;
            } else {
                const float4 ra = rs[a2], rp = rs[p];
                const float dx = ra.x - rp.x, dy = ra.y - rp.y, dz = ra.z - rp.z;
                const float d2   = fmaf(dx, dx, fmaf(dy, dy, dz * dz));
                const float invd = rsqrtf(d2);
                const float d    = d2 * invd;
                const float wf   = __expf(-d);
                const float gfs  = invd * INV_SIGMA;
                tabA[jp][al2] = make_float4(gfs, wf * C,
                                            invd * invd * INV_SIGMA, -dx * invd);
                tabB[jp][al2] = make_float2(-dy * invd, -dz * invd);
                gfsT[al2][jp] = gfs;
            }
        }
    }
    __syncthreads();

    const int   za = zs[a];
    const float gg = grid[g] * INV_SIGMA;
    const float bandlo = __shfl_sync(0xffffffffu, gg, 0)  - BAND;
    const float bandhi = __shfl_sync(0xffffffffu, gg, 31) + BAND;

    // 48-bit active-pair mask (warp-uniform).
    const float f0 = gfsT[al][lane];
    const unsigned b0m = __ballot_sync(0xffffffffu, f0 > bandlo && f0 < bandhi);
    const float f1 = (lane < 16) ? gfsT[al][32 + lane] : 0.f;
    const unsigned b1m = __ballot_sync(0xffffffffu,
                                       lane < 16 && f1 > bandlo && f1 < bandhi);
    const unsigned long long mask =
        (unsigned long long)b0m | ((unsigned long long)(b1m & 0xFFFFu) << 32);

    float* const mb = out + (((b * NE + za) * NE) * NG) + g;

    #pragma unroll
    for (int e = 0; e < NE; e++) {
        unsigned long long m =
            mask & ((1ull << segs[e + 1]) - (1ull << segs[e]));
        float wv = 0.f, xv = 0.f, yv = 0.f, zv = 0.f;
        while (m) {
            const int jp = __ffsll((long long)m) - 1;
            m &= m - 1;
            const float4 A  = tabA[jp][al];     // broadcast LDS
            const float2 Bv = tabB[jp][al];
            const float tt = gg - A.x;
            const float E  = ex2f((CM * tt) * tt);
            const float wg = A.y * E;
            const float s  = fmaf(wg * A.z, tt, wg);
            wv += wg;
            xv = fmaf(s, A.w,  xv);
            yv = fmaf(s, Bv.x, yv);
            zv = fmaf(s, Bv.y, zv);
        }
        // mbtr: coalesced RED.ADD per warp per segment.
        atomicAdd(mb + e * NG, wv);
        acc[e][lane][al * 3 + 0] = xv;
        acc[e][lane][al * 3 + 1] = yv;
        acc[e][lane][al * 3 + 2] = zv;
    }
    __syncthreads();

    // Float4 epilogue: 192 threads own one f4 (4 cells, spanning 2 atoms)
    // across all 16 slots. acc loaded once; 16 STG.128 per thread.
    if (t < NF4) {
        const int g2 = t / (ROWQ / 4);          // 0..31
        const int q4 = t - g2 * (ROWQ / 4);     // 0..5
        const int q0 = q4 * 4;

        float av[4][NE];
        int   zq[4];
        #pragma unroll
        for (int c = 0; c < 4; c++) {
            const int q = q0 + c;
            zq[c] = zs[third * ATH + q / 3];
            #pragma unroll
            for (int e = 0; e < NE; e++)
                av[c][e] = acc[e][g2][q];
        }

        float* const dbase = out + MBTR_SZ
            + ((size_t)(b * NE * NE) * NG + gchunk * GC + g2) * (NA * 3)
            + third * ROWQ + q0;

        #pragma unroll
        for (int slot = 0; slot < NE * NE; slot++) {
            const int e1 = slot >> 2, e2 = slot & 3;
            float4 v;
            float* vv = (float*)&v;
            #pragma unroll
            for (int c = 0; c < 4; c++) {
                vv[c] = (zq[c] == e1 ? av[c][e2] : 0.f)
                      + (zq[c] == e2 ? av[c][e1] : 0.f);
            }
            *(float4*)(dbase + (size_t)slot * (NG * NA * 3)) = v;
        }
    }
}

extern "C" void kernel_launch(void* const* d_in, const int* in_sizes, int n_in,
                              void* d_out, int out_size)
{
    const float* r    = (const float*)d_in[0];
    const int*   z    = (const int*)  d_in[1];
    const float* grid = (const float*)d_in[2];
    float*       out  = (float*)d_out;

    zero_mbtr<<<MBTR_SZ / 4096, 1024>>>((float4*)out);
    mbtr_kernel<<<NBLK, NTHR>>>(r, z, grid, out);
}

// round 15
// speedup vs baseline: 1.5160x; 1.5160x over previous
#include <cuda_runtime.h>

// MBTR + analytic divergence, GB300 (sm_103a). Round 12 = exact R8 revert
// (proven 22.5us kernel; R9/R10/R11 structural variants all neutral or
// spill-regressed) with the single validated constant change BAND 5.5->5.0
// (rel_err 3.3e-6, 300x under threshold).
//
// Block = (b, g-chunk of 32, atom-sixth of 8). Warp = one atom, lane = one g.
// Band skip: pair irrelevant to warp's 32-g window unless gfs in
// [gg_lo-5, gg_hi+5] sigma. Warp-uniform predicate -> 48-bit mask via 2
// ballots, iterate set bits. Table reads are warp-uniform LDS broadcasts.
// Div stores transposed through padded smem so global writes are dense.
// mbtr via coalesced global atomicAdd into pre-zeroed region.

#define NB   32
#define NA   48
#define NE   4
#define NG   128
#define ATH  8                  // atoms per block
#define GC   32                 // grid points per block
#define NTHR (ATH * GC)         // 256
#define NTHIRD (NA / ATH)       // 6
#define NGCH   (NG / GC)        // 4
#define NBLK (NB * NGCH * NTHIRD)   // 768
#define MBTR_SZ (NB * NE * NE * NG) // 65536
#define ROWQ (ATH * 3)          // 24 floats per (slot,g) row owned by block
#define ACCPAD (ROWQ + 1)       // 25: pad so g-strided STS is conflict-free

static __device__ __forceinline__ float ex2f(float x) {
    float y;
    asm("ex2.approx.ftz.f32 %0, %1;" : "=f"(y) : "f"(x));
    return y;
}

__global__ void zero_mbtr(float* __restrict__ out) {
    out[blockIdx.x * 1024 + threadIdx.x] = 0.f;   // 64 x 1024 = 65536
}

__global__ void __launch_bounds__(NTHR, 4)
mbtr_kernel(const float* __restrict__ r,
            const int*   __restrict__ z,
            const float* __restrict__ grid,
            float*       __restrict__ out)
{
    const int bid    = blockIdx.x;
    const int third  = bid % NTHIRD;
    const int tmp    = bid / NTHIRD;
    const int gchunk = tmp % NGCH;
    const int b      = tmp / NGCH;

    const int t    = threadIdx.x;
    const int al   = t >> 5;            // warp id = local atom
    const int lane = t & 31;
    const int a    = third * ATH + al;  // global atom
    const int g    = gchunk * GC + lane;

    __shared__ float4 tabA[NA][ATH];    // {gfs, wf*C, gsq, -ux}
    __shared__ float2 tabB[NA][ATH];    // {-uy, -uz}
    __shared__ float  gfsT[ATH][NA];    // gfs, lane-major readable
    __shared__ float  acc[NE][GC][ACCPAD];
    __shared__ float4 rs[NA];
    __shared__ int    zs[NA], S[NA], segs[NE + 1];

    const float INV_SIGMA = 20.0f;
    const float CM        = -0.72134752044448170f;   // -0.5 * log2(e)
    const float BAND      = 5.0f;                    // sigma units

    if (t < NA) {
        zs[t] = z[t];
        const float* rp = r + (b * NA + t) * 3;
        rs[t] = make_float4(rp[0], rp[1], rp[2], 0.f);
    }
    __syncthreads();

    if (t == 0) {
        int cnt[NE] = {0, 0, 0, 0};
        for (int j = 0; j < NA; j++) cnt[zs[j]]++;
        int off = 0, pos[NE];
        segs[0] = 0;
        #pragma unroll
        for (int e = 0; e < NE; e++) { pos[e] = off; off += cnt[e]; segs[e + 1] = off; }
        for (int j = 0; j < NA; j++) S[pos[zs[j]]++] = j;
    }
    __syncthreads();

    // Pair table: 48 partners x 8 local atoms = 384 entries over 256 threads.
    {
        const float gdx = grid[1] - grid[0];
        const float C   = gdx * 0.3989422804014327f * INV_SIGMA;
        for (int f = t; f < NA * ATH; f += NTHR) {
            const int jp  = f >> 3;
            const int al2 = f & (ATH - 1);
            const int a2  = third * ATH + al2;
            const int p   = S[jp];
            if (p == a2) {
                tabA[jp][al2] = make_float4(0.f, 0.f, 0.f, 0.f);
                tabB[jp][al2] = make_float2(0.f, 0.f);
                gfsT[al2][jp] = 0.f;
            } else {
                const float4 ra = rs[a2], rp = rs[p];
                const float dx = ra.x - rp.x, dy = ra.y - rp.y, dz = ra.z - rp.z;
                const float d2   = fmaf(dx, dx, fmaf(dy, dy, dz * dz));
                const float invd = rsqrtf(d2);
                const float d    = d2 * invd;
                const float wf   = __expf(-d);
                const float gfs  = invd * INV_SIGMA;
                tabA[jp][al2] = make_float4(gfs, wf * C,
                                            invd * invd * INV_SIGMA, -dx * invd);
                tabB[jp][al2] = make_float2(-dy * invd, -dz * invd);
                gfsT[al2][jp] = gfs;
            }
        }
    }
    __syncthreads();

    const int   za = zs[a];
    const float gg = grid[g] * INV_SIGMA;
    const float bandlo = __shfl_sync(0xffffffffu, gg, 0)  - BAND;
    const float bandhi = __shfl_sync(0xffffffffu, gg, 31) + BAND;

    // 48-bit active-pair mask (warp-uniform).
    const float f0 = gfsT[al][lane];
    const unsigned m0 = __ballot_sync(0xffffffffu, f0 > bandlo && f0 < bandhi);
    const float f1 = (lane < 16) ? gfsT[al][32 + lane] : 0.f;
    const unsigned m1 = __ballot_sync(0xffffffffu,
                                      lane < 16 && f1 > bandlo && f1 < bandhi);
    const unsigned long long mask =
        (unsigned long long)m0 | ((unsigned long long)(m1 & 0xFFFFu) << 32);

    float* const mb = out + (((b * NE + za) * NE) * NG) + g;

    #pragma unroll
    for (int e = 0; e < NE; e++) {
        unsigned long long m =
            mask & ((1ull << segs[e + 1]) - (1ull << segs[e]));
        float wv = 0.f, xv = 0.f, yv = 0.f, zv = 0.f;
        while (m) {
            const int jp = __ffsll((long long)m) - 1;
            m &= m - 1;
            const float4 A  = tabA[jp][al];     // broadcast LDS
            const float2 Bv = tabB[jp][al];
            const float tt = gg - A.x;
            const float E  = ex2f((CM * tt) * tt);
            const float wg = A.y * E;
            const float s  = fmaf(wg * A.z, tt, wg);
            wv += wg;
            xv = fmaf(s, A.w,  xv);
            yv = fmaf(s, Bv.x, yv);
            zv = fmaf(s, Bv.y, zv);
        }
        // mbtr: coalesced 128B RED.ADD per warp per segment.
        atomicAdd(mb + e * NG, wv);
        // stash for transposed store
        acc[e][lane][al * 3 + 0] = xv;
        acc[e][lane][al * 3 + 1] = yv;
        acc[e][lane][al * 3 + 2] = zv;
    }
    __syncthreads();

    // Transposed div store: 16 slots x 32 g x 24 floats = 12288 per block.
    // Thread handles 3 fixed (g,q) cells per slot -> dense rows.
    int gq[3], qq[3], zaq[3];
    #pragma unroll
    for (int k = 0; k < 3; k++) {
        const int f = k * NTHR + t;
        gq[k]  = f / ROWQ;
        qq[k]  = f - gq[k] * ROWQ;
        zaq[k] = zs[third * ATH + qq[k] / 3];
    }
    float* __restrict__ dbase = out + MBTR_SZ
        + ((size_t)(b * NE * NE) * NG + gchunk * GC) * (NA * 3)
        + third * ROWQ;

    #pragma unroll
    for (int slot = 0; slot < NE * NE; slot++) {
        const int e1 = slot >> 2, e2 = slot & 3;
        #pragma unroll
        for (int k = 0; k < 3; k++) {
            float v = 0.f;
            if (zaq[k] == e1) v += acc[e2][gq[k]][qq[k]];
            if (zaq[k] == e2) v += acc[e1][gq[k]][qq[k]];
            dbase[(size_t)slot * (NG * NA * 3) + gq[k] * (NA * 3) + qq[k]] = v;
        }
    }
}

extern "C" void kernel_launch(void* const* d_in, const int* in_sizes, int n_in,
                              void* d_out, int out_size)
{
    const float* r    = (const float*)d_in[0];
    const int*   z    = (const int*)  d_in[1];
    const float* grid = (const float*)d_in[2];
    float*       out  = (float*)d_out;

    zero_mbtr<<<MBTR_SZ / 1024, 1024>>>(out);
    mbtr_kernel<<<NBLK, NTHR>>>(r, z, grid, out);
}